// round 9
// baseline (speedup 1.0000x reference)
#include <cuda_runtime.h>

#define IN_DIM   8192
#define OUT_DIM  16384
#define TOPK     327
#define ROW_SPLITS 37                 // 16 * 37 = 592 = 4 * 148 SMs → one even wave
#define ROWS_PER_SPLIT 222            // ceil(8192 / 37)
#define COL_BLOCKS 16                 // 16 blocks * 256 thr * 4 cols = 16384 cols
#define CNT_ONE  (1u << 20)           // arrival counter packed above the value
#define VAL_MASK 0xFFFFFu             // overlap value ≤ 8192 fits easily

__device__ unsigned g_overlap[OUT_DIM];   // [counter:12 | value:20]; zeroed at load & by finalize
__device__ int      g_hist[IN_DIM + 1];   // zeroed at load & by finalize

// finalize sync state — all zero at load; finalize restores zeros before exit
__device__ int g_T, g_R;
__device__ int g_Tready;
__device__ int g_tieseg[16];
__device__ int g_cnt1;
__device__ int g_cnt2;

__device__ __forceinline__ int warp_incl_scan(int v) {
    int lane = threadIdx.x & 31;
#pragma unroll
    for (int o = 1; o < 32; o <<= 1) {
        int n = __shfl_up_sync(0xffffffffu, v, o);
        if (lane >= o) v += n;
    }
    return v;
}

// ---------------------------------------------------------------------------
// Kernel 1: binarized GEMV with fused histogram (unchanged from R8).
// round(p) for p ~ U[0,1) under round-half-even == (p > 0.5f).
// ---------------------------------------------------------------------------
__global__ void __launch_bounds__(256, 4)
gemv_kernel(const float* __restrict__ p, const int* __restrict__ x) {
    __shared__ int s_act[ROWS_PER_SPLIT];
    __shared__ int s_wbase[8];
    __shared__ int s_na;

    int t    = threadIdx.x;
    int lane = t & 31;
    int w    = t >> 5;

    int r0 = blockIdx.y * ROWS_PER_SPLIT;
    int r1 = min(r0 + ROWS_PER_SPLIT, IN_DIM);
    int n  = r1 - r0;

    int flag = 0;
    if (t < n) flag = (x[r0 + t] != 0);
    unsigned m = __ballot_sync(0xffffffffu, flag);
    int pos = __popc(m & ((1u << lane) - 1u));
    if (lane == 0) s_wbase[w] = __popc(m);
    __syncthreads();
    if (t < 8) {
        int v = s_wbase[t];
        int inc = v;
#pragma unroll
        for (int o = 1; o < 8; o <<= 1) {
            int u = __shfl_up_sync(0xffu, inc, o);
            if (t >= o) inc += u;
        }
        s_wbase[t] = inc - v;
        if (t == 7) s_na = inc;
    }
    __syncthreads();
    if (flag) s_act[s_wbase[w] + pos] = r0 + t;
    __syncthreads();

    int na = s_na;

    int col = (blockIdx.x * blockDim.x + t) * 4;
    const float4* pc = reinterpret_cast<const float4*>(p + col);

    unsigned c0 = 0, c1 = 0, c2 = 0, c3 = 0;
    int r = 0;
    for (; r + 8 <= na; r += 8) {
        float4 v[8];
#pragma unroll
        for (int u = 0; u < 8; u++)
            v[u] = __ldcs(pc + (size_t)s_act[r + u] * (OUT_DIM / 4));
#pragma unroll
        for (int u = 0; u < 8; u++) {
            c0 += (v[u].x > 0.5f);
            c1 += (v[u].y > 0.5f);
            c2 += (v[u].z > 0.5f);
            c3 += (v[u].w > 0.5f);
        }
    }
    for (; r < na; r++) {
        float4 v0 = __ldcs(pc + (size_t)s_act[r] * (OUT_DIM / 4));
        c0 += (v0.x > 0.5f);
        c1 += (v0.y > 0.5f);
        c2 += (v0.z > 0.5f);
        c3 += (v0.w > 0.5f);
    }

    unsigned cc[4] = {c0, c1, c2, c3};
#pragma unroll
    for (int u = 0; u < 4; u++) {
        unsigned old = atomicAdd(&g_overlap[col + u], CNT_ONE + cc[u]);
        if ((old >> 20) == (ROW_SPLITS - 1)) {
            int final_v = (int)((old & VAL_MASK) + cc[u]);
            atomicAdd(&g_hist[final_v], 1);
        }
    }
}

// ---------------------------------------------------------------------------
// Kernel 2: parallel finalize. 17 blocks, single wave, atomic spin-phases.
//   block 16     : threshold (T, R) from histogram; zero g_hist; reset sync.
//   blocks 0..15 : output segment of 1024 columns each, exact jax.lax.top_k
//                  tie semantics (lower index first); zero g_overlap slice.
// All sync globals are returned to zero before the kernel ends, so graph
// replays are deterministic.
// ---------------------------------------------------------------------------
__global__ void __launch_bounds__(1024)
finalize_kernel(float* __restrict__ out) {
    __shared__ int s_hist[IN_DIM + 1];
    __shared__ int s_scan[1024];
    __shared__ int s_warp[32];
    __shared__ int s_wexc[32];
    __shared__ int s_seg[16];
    __shared__ int s_T, s_R, s_total;

    int tid  = threadIdx.x;
    int lane = tid & 31;
    int wid  = tid >> 5;
    int b    = blockIdx.x;

    if (b == 16) {
        // ---- threshold block ----
        for (int i = tid; i <= IN_DIM; i += 1024) s_hist[i] = g_hist[i];
        __syncthreads();

        int b0 = tid * 8;
        int csum = 0;
#pragma unroll
        for (int k = 0; k < 8; k++) csum += s_hist[b0 + k];
        if (tid == 1023) csum += s_hist[IN_DIM];

        s_scan[1023 - tid] = csum;       // reversed → prefix scan = suffix scan
        __syncthreads();
        {
            int v = s_scan[tid];
            int inc = warp_incl_scan(v);
            if (lane == 31) s_warp[wid] = inc;
            __syncthreads();
            if (wid == 0) {
                int wv = s_warp[lane];
                s_warp[lane] = warp_incl_scan(wv);
            }
            __syncthreads();
            int add = (wid > 0) ? s_warp[wid - 1] : 0;
            s_scan[tid] = inc + add;
        }
        __syncthreads();

        int above = (tid == 1023) ? 0 : s_scan[1022 - tid];
        {
            int running = above;
            int top = (tid == 1023) ? IN_DIM : (b0 + 7);
            for (int v = top; v >= b0; v--) {
                int prev = running;          // count(> v)
                running += s_hist[v];        // count(>= v)
                if (prev < TOPK && running >= TOPK) {
                    g_T = v;
                    g_R = TOPK - prev;
                }
            }
        }
        __syncthreads();                      // g_T/g_R stores done block-wide
        __threadfence();
        if (tid == 0) atomicExch(&g_Tready, 1);

        // zero the histogram for the next launch
        for (int i = tid; i <= IN_DIM; i += 1024) g_hist[i] = 0;

        // wait for all worker blocks, then reset sync state
        if (tid == 0) {
            while (atomicAdd(&g_cnt2, 0) < 16) { }
            atomicExch(&g_Tready, 0);
            atomicExch(&g_cnt1, 0);
            atomicExch(&g_cnt2, 0);
        }
    } else {
        // ---- worker block: columns [b*1024, b*1024+1024) ----
        int colbase = b * 1024;
        int ov = (int)(g_overlap[colbase + tid] & VAL_MASK);  // preload early

        if (tid == 0) {
            while (atomicAdd(&g_Tready, 0) == 0) { }
            __threadfence();
            s_T = g_T;
            s_R = g_R;
        }
        __syncthreads();
        int T = s_T;
        int R = s_R;

        int flag = (ov == T);
        unsigned m = __ballot_sync(0xffffffffu, flag);
        if (lane == 0) s_warp[wid] = __popc(m);
        __syncthreads();
        if (wid == 0) {
            int v = s_warp[lane];
            int inc = warp_incl_scan(v);
            s_wexc[lane] = inc - v;           // exclusive per-warp base
            if (lane == 31) s_total = inc;
        }
        __syncthreads();

        if (tid == 0) {
            g_tieseg[b] = s_total;
            __threadfence();
            atomicAdd(&g_cnt1, 1);
            while (atomicAdd(&g_cnt1, 0) < 16) { }
            __threadfence();
        }
        __syncthreads();

        if (tid < 16) s_seg[tid] = g_tieseg[tid];
        __syncthreads();

        int base = 0;
        for (int j = 0; j < b; j++) base += s_seg[j];

        int rank = base + s_wexc[wid] + __popc(m & ((1u << lane) - 1u));
        float val = 0.0f;
        if (ov > T) val = 1.0f;
        else if (flag && rank < R) val = 1.0f;
        out[colbase + tid] = val;

        g_overlap[colbase + tid] = 0u;        // reset accumulator slice

        __syncthreads();
        __threadfence();
        if (tid == 0) atomicAdd(&g_cnt2, 1);
    }
}

extern "C" void kernel_launch(void* const* d_in, const int* in_sizes, int n_in,
                              void* d_out, int out_size) {
    const int*   x = (const int*)d_in[0];
    const float* p = (const float*)d_in[1];
    if (in_sizes[0] != IN_DIM) {
        x = (const int*)d_in[1];
        p = (const float*)d_in[0];
    }
    float* out = (float*)d_out;

    dim3 grid(COL_BLOCKS, ROW_SPLITS);
    gemv_kernel<<<grid, 256>>>(p, x);
    finalize_kernel<<<17, 1024>>>(out);
}